// round 12
// baseline (speedup 1.0000x reference)
#include <cuda_runtime.h>
#include <cuda_bf16.h>
#include <cstdint>

#define Bb 2
#define Nn 3136
#define Cc 256
#define Hh 56
#define Mtot (Bb * Nn)   // 6272

// ---------------- scratch (allocation-free) ----------------
__device__ float g_Q[Mtot * Cc];
__device__ float g_K[Mtot * Cc];
__device__ float g_V[Mtot * Cc];
__device__ __nv_bfloat16 g_xhi[Mtot * Cc], g_xlo[Mtot * Cc];
__device__ __nv_bfloat16 g_kvhi[Mtot * Cc], g_kvlo[Mtot * Cc];
__device__ __nv_bfloat16 g_ahi[Mtot * Cc], g_alo[Mtot * Cc];
__device__ __nv_bfloat16 g_whi[4 * Cc * Cc], g_wlo[4 * Cc * Cc];

// ---------------- portable (sm_80+) PTX helpers ----------------
__device__ __forceinline__ uint32_t smem_u32(const void* p) {
    uint32_t a;
    asm("{ .reg .u64 t; cvta.to.shared.u64 t, %1; cvt.u32.u64 %0, t; }" : "=r"(a) : "l"(p));
    return a;
}
__device__ __forceinline__ void cp_async16(uint32_t dst, const void* src) {
    asm volatile("cp.async.cg.shared.global [%0], [%1], 16;" :: "r"(dst), "l"(src) : "memory");
}
__device__ __forceinline__ void cp_commit() { asm volatile("cp.async.commit_group;" ::: "memory"); }
__device__ __forceinline__ void cp_wait1() { asm volatile("cp.async.wait_group 1;" ::: "memory"); }
__device__ __forceinline__ void cp_wait0() { asm volatile("cp.async.wait_group 0;" ::: "memory"); }
__device__ __forceinline__ void ldsm4(uint32_t* r, uint32_t addr) {
    asm volatile("ldmatrix.sync.aligned.m8n8.x4.shared.b16 {%0,%1,%2,%3}, [%4];"
                 : "=r"(r[0]), "=r"(r[1]), "=r"(r[2]), "=r"(r[3]) : "r"(addr));
}
__device__ __forceinline__ void mma16816(float* d, const uint32_t* a, const uint32_t* b) {
    asm volatile(
        "mma.sync.aligned.m16n8k16.row.col.f32.bf16.bf16.f32 "
        "{%0,%1,%2,%3}, {%4,%5,%6,%7}, {%8,%9}, {%0,%1,%2,%3};"
        : "+f"(d[0]), "+f"(d[1]), "+f"(d[2]), "+f"(d[3])
        : "r"(a[0]), "r"(a[1]), "r"(a[2]), "r"(a[3]), "r"(b[0]), "r"(b[1]));
}

struct alignas(8) bf16x4 { __nv_bfloat162 a, b; };

// ---------------------------------------------------------------------------
// Fused split: all 6 fp32 tensors -> (hi, lo) bf16 pairs, one launch.
// ---------------------------------------------------------------------------
__global__ __launch_bounds__(256) void split_all(
    const float4* __restrict__ x, const float4* __restrict__ xkv,
    const float4* __restrict__ wq, const float4* __restrict__ wk,
    const float4* __restrict__ wv, const float4* __restrict__ wp,
    __nv_bfloat162* __restrict__ xhi, __nv_bfloat162* __restrict__ xlo,
    __nv_bfloat162* __restrict__ kvhi, __nv_bfloat162* __restrict__ kvlo,
    __nv_bfloat162* __restrict__ whi, __nv_bfloat162* __restrict__ wlo) {
    int blk = blockIdx.x;
    const float4* src;
    __nv_bfloat162 *ho, *lo_;
    int idx;
    if (blk < 1568) {
        src = x; ho = xhi; lo_ = xlo; idx = blk;
    } else if (blk < 3136) {
        src = xkv; ho = kvhi; lo_ = kvlo; idx = blk - 1568;
    } else {
        int w = (blk - 3136) >> 6;
        idx = (blk - 3136) & 63;
        src = (w == 0) ? wq : (w == 1) ? wk : (w == 2) ? wv : wp;
        ho = whi + w * 32768;
        lo_ = wlo + w * 32768;
    }
    int i = idx * 256 + threadIdx.x;
    float4 v = src[i];
    __nv_bfloat16 h0 = __float2bfloat16(v.x), h1 = __float2bfloat16(v.y);
    __nv_bfloat16 h2 = __float2bfloat16(v.z), h3 = __float2bfloat16(v.w);
    ho[2 * i + 0] = __nv_bfloat162(h0, h1);
    ho[2 * i + 1] = __nv_bfloat162(h2, h3);
    lo_[2 * i + 0] = __nv_bfloat162(__float2bfloat16(v.x - __bfloat162float(h0)),
                                    __float2bfloat16(v.y - __bfloat162float(h1)));
    lo_[2 * i + 1] = __nv_bfloat162(__float2bfloat16(v.z - __bfloat162float(h2)),
                                    __float2bfloat16(v.w - __bfloat162float(h3)));
}

// ---------------------------------------------------------------------------
// HMMA GEMM body (R7/R10 measured-best): out = AH@WH^T + AH@WL^T + AL@WH^T
// 256 threads = 8 warps, warp grid 4m x 2n, warp tile 16x32, block 64x64.
// Split accumulators; 3-stage depth-2 cp.async pipeline; one sync per chunk.
// Smem rows padded to 40 bf16 (80B) -> conflict-free ldmatrix.
// ---------------------------------------------------------------------------
#define SM_MAT   5120          // 64 * 40 * 2
#define SM_STAGE 20480         // 4 * SM_MAT
#define N_STAGE  3
#define SMEM_BYTES (N_STAGE * SM_STAGE + 256)

__device__ __forceinline__ void gemm_body(const __nv_bfloat16* __restrict__ Ahi,
                                          const __nv_bfloat16* __restrict__ Alo,
                                          const __nv_bfloat16* __restrict__ Whi,
                                          const __nv_bfloat16* __restrict__ Wlo,
                                          float* __restrict__ out,
                                          const float* __restrict__ bias,
                                          int m0, int n0, char* sm) {
    uint32_t smu = smem_u32(sm);
    float* bsm = (float*)(sm + N_STAGE * SM_STAGE);

    const int tid = threadIdx.x;
    const int wid = tid >> 5, lane = tid & 31;
    const int wm = (wid & 3) * 16, wn = (wid >> 2) * 32;

    if (tid < 64) bsm[tid] = bias ? bias[n0 + tid] : 0.0f;

    const __nv_bfloat16* aH = Ahi + (size_t)m0 * Cc;
    const __nv_bfloat16* aL = Alo + (size_t)m0 * Cc;
    const __nv_bfloat16* wH = Whi + (size_t)n0 * Cc;
    const __nv_bfloat16* wL = Wlo + (size_t)n0 * Cc;

    const int lrow = tid >> 2, lj = tid & 3;  // 64 rows x 4 vec16 per mat

    auto load_chunk = [&](int s, int c) {
        int k0 = c * 32;
        uint32_t sb = smu + s * SM_STAGE + lrow * 80 + lj * 16;
        size_t go = (size_t)lrow * Cc + k0 + lj * 8;
        cp_async16(sb,              aH + go);
        cp_async16(sb + SM_MAT,     aL + go);
        cp_async16(sb + 2 * SM_MAT, wH + go);
        cp_async16(sb + 3 * SM_MAT, wL + go);
        cp_commit();
    };

    float accA[4][4], accB[4][4];
#pragma unroll
    for (int a = 0; a < 4; a++)
#pragma unroll
        for (int b = 0; b < 4; b++) { accA[a][b] = 0.0f; accB[a][b] = 0.0f; }

    load_chunk(0, 0);
    load_chunk(1, 1);

    const int r = lane & 15, kh = lane >> 4;

    for (int c = 0; c < 8; c++) {
        if (c < 7) cp_wait1();
        else       cp_wait0();
        __syncthreads();
        if (c + 2 < 8) load_chunk((c + 2) % N_STAGE, c + 2);

        int cur = c % N_STAGE;
        uint32_t sAH = smu + cur * SM_STAGE;
        uint32_t sAL = sAH + SM_MAT;
        uint32_t sWH = sAH + 2 * SM_MAT;
        uint32_t sWL = sAH + 3 * SM_MAT;

#pragma unroll
        for (int ks = 0; ks < 2; ks++) {
            int kcol = ks * 16 + kh * 8;
            uint32_t AH[4], AL[4], BH[4][2], BL[4][2];
            {
                uint32_t off = (uint32_t)((wm + r) * 40 + kcol) * 2;
                ldsm4(AH, sAH + off);
                ldsm4(AL, sAL + off);
            }
#pragma unroll
            for (int nj = 0; nj < 2; nj++) {
                uint32_t off = (uint32_t)((wn + nj * 16 + r) * 40 + kcol) * 2;
                uint32_t th[4], tl[4];
                ldsm4(th, sWH + off);
                ldsm4(tl, sWL + off);
                BH[nj * 2 + 0][0] = th[0]; BH[nj * 2 + 0][1] = th[2];
                BH[nj * 2 + 1][0] = th[1]; BH[nj * 2 + 1][1] = th[3];
                BL[nj * 2 + 0][0] = tl[0]; BL[nj * 2 + 0][1] = tl[2];
                BL[nj * 2 + 1][0] = tl[1]; BL[nj * 2 + 1][1] = tl[3];
            }
#pragma unroll
            for (int ni = 0; ni < 4; ni++) mma16816(accA[ni], AH, BH[ni]);
#pragma unroll
            for (int ni = 0; ni < 4; ni++) mma16816(accB[ni], AH, BL[ni]);
#pragma unroll
            for (int ni = 0; ni < 4; ni++) mma16816(accB[ni], AL, BH[ni]);
        }
    }

    const int g = lane >> 2, tg = lane & 3;
#pragma unroll
    for (int ni = 0; ni < 4; ni++) {
        int row = m0 + wm + g;
        int coll = wn + ni * 8 + tg * 2;
        int col = n0 + coll;
        float2 v0 = make_float2(accA[ni][0] + accB[ni][0] + bsm[coll],
                                accA[ni][1] + accB[ni][1] + bsm[coll + 1]);
        float2 v1 = make_float2(accA[ni][2] + accB[ni][2] + bsm[coll],
                                accA[ni][3] + accB[ni][3] + bsm[coll + 1]);
        *(float2*)(out + (size_t)row * Cc + col) = v0;
        *(float2*)(out + (size_t)(row + 8) * Cc + col) = v1;
    }
}

// Fused Q/K/V projections: grid (98, 4, 3); z selects {x@Wq, xkv@Wk, xkv@Wv}.
__global__ __launch_bounds__(256, 3) void gemm_qkv(
    const __nv_bfloat16* __restrict__ xhi, const __nv_bfloat16* __restrict__ xlo,
    const __nv_bfloat16* __restrict__ kvhi, const __nv_bfloat16* __restrict__ kvlo,
    const __nv_bfloat16* __restrict__ whi, const __nv_bfloat16* __restrict__ wlo,
    float* __restrict__ Q, float* __restrict__ K, float* __restrict__ V) {
    extern __shared__ char sm[];
    int z = blockIdx.z;
    const __nv_bfloat16* Ahi = (z == 0) ? xhi : kvhi;
    const __nv_bfloat16* Alo = (z == 0) ? xlo : kvlo;
    const __nv_bfloat16* Wh = whi + (size_t)z * 65536;
    const __nv_bfloat16* Wl = wlo + (size_t)z * 65536;
    float* out = (z == 0) ? Q : (z == 1) ? K : V;
    gemm_body(Ahi, Alo, Wh, Wl, out, nullptr, blockIdx.x * 64, blockIdx.y * 64, sm);
}

// Output projection (with bias).
__global__ __launch_bounds__(256, 3) void gemm_out(
    const __nv_bfloat16* __restrict__ Ahi, const __nv_bfloat16* __restrict__ Alo,
    const __nv_bfloat16* __restrict__ Whi, const __nv_bfloat16* __restrict__ Wlo,
    float* __restrict__ out, const float* __restrict__ bias) {
    extern __shared__ char sm[];
    gemm_body(Ahi, Alo, Whi, Wlo, out, bias, blockIdx.x * 64, blockIdx.y * 64, sm);
}

// ---------------------------------------------------------------------------
// Local windowed attention (radius 3 -> 29 neighbors), SINGLE PASS.
// Block = 8x4 spatial query patch (32 queries), 512 threads, 16 thr/query;
// thread owns 16 channels (half a head) -> dot = partial + ONE shfl_xor(1).
// Patch tiling: neighborhood union ~14x10=140 rows per 32 queries
// (4.4 rows/query vs 12.3 for the 8-in-a-row layout) -> ~2.8x less L2 traffic.
// No max subtraction (scores O(1); softmax shift-invariant).
// ---------------------------------------------------------------------------
__global__ __launch_bounds__(512) void local_attn(const float* __restrict__ Q,
                                                  const float* __restrict__ K,
                                                  const float* __restrict__ V,
                                                  __nv_bfloat16* __restrict__ Ohi,
                                                  __nv_bfloat16* __restrict__ Olo) {
    const int pid = blockIdx.x;          // 0..195 (98 patches/image x 2)
    const int b  = pid / 98;
    const int pp = pid - b * 98;         // 7 (y) x 14 (x) patches of 8x4
    const int py = (pp / 14) * 8;
    const int px = (pp % 14) * 4;

    const int qi = threadIdx.x >> 4;     // query in patch (0..31)
    const int t  = threadIdx.x & 15;     // channel group (16 ch each)
    const int qy = py + (qi >> 2);
    const int qx = px + (qi & 3);
    const int n  = qy * Hh + qx;
    const int bn = b * Nn + n;

    const float scale = 0.17677669529663687f;  // 32^-0.5
    const size_t coff = (size_t)bn * Cc + t * 16;
    float4 q[4];
#pragma unroll
    for (int j = 0; j < 4; j++) {
        q[j] = *(const float4*)(Q + coff + j * 4);
        q[j].x *= scale; q[j].y *= scale; q[j].z *= scale; q[j].w *= scale;
    }

    const int dy[29] = {-3,-2,-2,-2,-2,-2,-1,-1,-1,-1,-1, 0, 0, 0, 0, 0, 0, 0,
                         1, 1, 1, 1, 1, 2, 2, 2, 2, 2, 3};
    const int dx[29] = { 0,-2,-1, 0, 1, 2,-2,-1, 0, 1, 2,-3,-2,-1, 0, 1, 2, 3,
                        -2,-1, 0, 1, 2,-2,-1, 0, 1, 2, 0};

    const size_t base = (size_t)b * Nn;
    float s = 0.f;
    float4 acc[4];
#pragma unroll
    for (int j = 0; j < 4; j++) acc[j] = make_float4(0.f, 0.f, 0.f, 0.f);

#pragma unroll
    for (int i = 0; i < 29; i++) {
        int ny = qy + dy[i], nx = qx + dx[i];
        bool ok = ((unsigned)ny < (unsigned)Hh) && ((unsigned)nx < (unsigned)Hh);
        int nn = ok ? ny * Hh + nx : n;
        const float* kp = K + (base + nn) * Cc + t * 16;
        const float* vp = V + (base + nn) * Cc + t * 16;
        float p = 0.f;
#pragma unroll
        for (int j = 0; j < 4; j++) {
            float4 k4 = *(const float4*)(kp + j * 4);
            p = fmaf(q[j].x, k4.x, p);
            p = fmaf(q[j].y, k4.y, p);
            p = fmaf(q[j].z, k4.z, p);
            p = fmaf(q[j].w, k4.w, p);
        }
        p += __shfl_xor_sync(0xffffffffu, p, 1);   // partner half of the head
        float e = ok ? __expf(p) : 0.f;
        s += e;
#pragma unroll
        for (int j = 0; j < 4; j++) {
            float4 v4 = *(const float4*)(vp + j * 4);
            acc[j].x = fmaf(e, v4.x, acc[j].x);
            acc[j].y = fmaf(e, v4.y, acc[j].y);
            acc[j].z = fmaf(e, v4.z, acc[j].z);
            acc[j].w = fmaf(e, v4.w, acc[j].w);
        }
    }

    float inv = __fdividef(1.0f, s);
#pragma unroll
    for (int j = 0; j < 4; j++) {
        float4 o = make_float4(acc[j].x * inv, acc[j].y * inv,
                               acc[j].z * inv, acc[j].w * inv);
        __nv_bfloat16 h0 = __float2bfloat16(o.x), h1 = __float2bfloat16(o.y);
        __nv_bfloat16 h2 = __float2bfloat16(o.z), h3 = __float2bfloat16(o.w);
        bf16x4 hv, lv;
        hv.a = __nv_bfloat162(h0, h1);
        hv.b = __nv_bfloat162(h2, h3);
        lv.a = __nv_bfloat162(__float2bfloat16(o.x - __bfloat162float(h0)),
                              __float2bfloat16(o.y - __bfloat162float(h1)));
        lv.b = __nv_bfloat162(__float2bfloat16(o.z - __bfloat162float(h2)),
                              __float2bfloat16(o.w - __bfloat162float(h3)));
        *(bf16x4*)(Ohi + coff + j * 4) = hv;
        *(bf16x4*)(Olo + coff + j * 4) = lv;
    }
}

// ---------------------------------------------------------------------------
extern "C" void kernel_launch(void* const* d_in, const int* in_sizes, int n_in,
                              void* d_out, int out_size) {
    const float* x   = (const float*)d_in[0];
    const float* xkv = (const float*)d_in[1];
    const float* Wq  = (const float*)d_in[2];
    const float* Wk  = (const float*)d_in[3];
    const float* Wv  = (const float*)d_in[4];
    const float* Wp  = (const float*)d_in[5];
    const float* bp  = (const float*)d_in[6];
    float* out = (float*)d_out;

    float *Qp, *Kp, *Vp;
    __nv_bfloat16 *xhi, *xlo, *kvhi, *kvlo, *ahi, *alo, *whi, *wlo;
    cudaGetSymbolAddress((void**)&Qp, g_Q);
    cudaGetSymbolAddress((void**)&Kp, g_K);
    cudaGetSymbolAddress((void**)&Vp, g_V);
    cudaGetSymbolAddress((void**)&xhi, g_xhi);
    cudaGetSymbolAddress((void**)&xlo, g_xlo);
    cudaGetSymbolAddress((void**)&kvhi, g_kvhi);
    cudaGetSymbolAddress((void**)&kvlo, g_kvlo);
    cudaGetSymbolAddress((void**)&ahi, g_ahi);
    cudaGetSymbolAddress((void**)&alo, g_alo);
    cudaGetSymbolAddress((void**)&whi, g_whi);
    cudaGetSymbolAddress((void**)&wlo, g_wlo);

    cudaFuncSetAttribute(gemm_qkv, cudaFuncAttributeMaxDynamicSharedMemorySize, SMEM_BYTES);
    cudaFuncSetAttribute(gemm_out, cudaFuncAttributeMaxDynamicSharedMemorySize, SMEM_BYTES);

    split_all<<<3392, 256>>>((const float4*)x, (const float4*)xkv,
                             (const float4*)Wq, (const float4*)Wk,
                             (const float4*)Wv, (const float4*)Wp,
                             (__nv_bfloat162*)xhi, (__nv_bfloat162*)xlo,
                             (__nv_bfloat162*)kvhi, (__nv_bfloat162*)kvlo,
                             (__nv_bfloat162*)whi, (__nv_bfloat162*)wlo);

    dim3 gqkv(Mtot / 64, Cc / 64, 3);   // (98, 4, 3) = 1176 CTAs
    gemm_qkv<<<gqkv, 256, SMEM_BYTES>>>(xhi, xlo, kvhi, kvlo, whi, wlo, Qp, Kp, Vp);

    local_attn<<<Mtot / 32, 512>>>(Qp, Kp, Vp, ahi, alo);

    dim3 gout(Mtot / 64, Cc / 64);      // (98, 4) = 392 CTAs
    gemm_out<<<gout, 256, SMEM_BYTES>>>(ahi, alo, whi + 196608, wlo + 196608, out, bp);
}

// round 13
// speedup vs baseline: 1.1356x; 1.1356x over previous
#include <cuda_runtime.h>
#include <cuda_bf16.h>
#include <cstdint>

#define Bb 2
#define Nn 3136
#define Cc 256
#define Hh 56
#define Mtot (Bb * Nn)   // 6272

// ---------------- scratch (allocation-free) ----------------
__device__ float g_Q[Mtot * Cc];
__device__ float g_K[Mtot * Cc];
__device__ float g_V[Mtot * Cc];
__device__ __nv_bfloat16 g_xhi[Mtot * Cc], g_xlo[Mtot * Cc];
__device__ __nv_bfloat16 g_kvhi[Mtot * Cc], g_kvlo[Mtot * Cc];
__device__ __nv_bfloat16 g_ahi[Mtot * Cc], g_alo[Mtot * Cc];
__device__ __nv_bfloat16 g_whi[4 * Cc * Cc], g_wlo[4 * Cc * Cc];

// ---------------- portable (sm_80+) PTX helpers ----------------
__device__ __forceinline__ uint32_t smem_u32(const void* p) {
    uint32_t a;
    asm("{ .reg .u64 t; cvta.to.shared.u64 t, %1; cvt.u32.u64 %0, t; }" : "=r"(a) : "l"(p));
    return a;
}
__device__ __forceinline__ void cp_async16(uint32_t dst, const void* src) {
    asm volatile("cp.async.cg.shared.global [%0], [%1], 16;" :: "r"(dst), "l"(src) : "memory");
}
__device__ __forceinline__ void cp_commit() { asm volatile("cp.async.commit_group;" ::: "memory"); }
__device__ __forceinline__ void cp_wait2() { asm volatile("cp.async.wait_group 2;" ::: "memory"); }
__device__ __forceinline__ void cp_wait1() { asm volatile("cp.async.wait_group 1;" ::: "memory"); }
__device__ __forceinline__ void cp_wait0() { asm volatile("cp.async.wait_group 0;" ::: "memory"); }
__device__ __forceinline__ void ldsm4(uint32_t* r, uint32_t addr) {
    asm volatile("ldmatrix.sync.aligned.m8n8.x4.shared.b16 {%0,%1,%2,%3}, [%4];"
                 : "=r"(r[0]), "=r"(r[1]), "=r"(r[2]), "=r"(r[3]) : "r"(addr));
}
__device__ __forceinline__ void mma16816(float* d, const uint32_t* a, const uint32_t* b) {
    asm volatile(
        "mma.sync.aligned.m16n8k16.row.col.f32.bf16.bf16.f32 "
        "{%0,%1,%2,%3}, {%4,%5,%6,%7}, {%8,%9}, {%0,%1,%2,%3};"
        : "+f"(d[0]), "+f"(d[1]), "+f"(d[2]), "+f"(d[3])
        : "r"(a[0]), "r"(a[1]), "r"(a[2]), "r"(a[3]), "r"(b[0]), "r"(b[1]));
}

struct alignas(8) bf16x4 { __nv_bfloat162 a, b; };

// ---------------------------------------------------------------------------
// Fused split: all 6 fp32 tensors -> (hi, lo) bf16 pairs, one launch.
// Wq is pre-multiplied by the softmax scale (hd^-0.5) so Q comes out scaled.
// ---------------------------------------------------------------------------
__global__ __launch_bounds__(256) void split_all(
    const float4* __restrict__ x, const float4* __restrict__ xkv,
    const float4* __restrict__ wq, const float4* __restrict__ wk,
    const float4* __restrict__ wv, const float4* __restrict__ wp,
    __nv_bfloat162* __restrict__ xhi, __nv_bfloat162* __restrict__ xlo,
    __nv_bfloat162* __restrict__ kvhi, __nv_bfloat162* __restrict__ kvlo,
    __nv_bfloat162* __restrict__ whi, __nv_bfloat162* __restrict__ wlo) {
    int blk = blockIdx.x;
    const float4* src;
    __nv_bfloat162 *ho, *lo_;
    int idx;
    float mul = 1.0f;
    if (blk < 1568) {
        src = x; ho = xhi; lo_ = xlo; idx = blk;
    } else if (blk < 3136) {
        src = xkv; ho = kvhi; lo_ = kvlo; idx = blk - 1568;
    } else {
        int w = (blk - 3136) >> 6;
        idx = (blk - 3136) & 63;
        src = (w == 0) ? wq : (w == 1) ? wk : (w == 2) ? wv : wp;
        ho = whi + w * 32768;
        lo_ = wlo + w * 32768;
        if (w == 0) mul = 0.17677669529663687f;   // fold 32^-0.5 into Wq
    }
    int i = idx * 256 + threadIdx.x;
    float4 v = src[i];
    v.x *= mul; v.y *= mul; v.z *= mul; v.w *= mul;
    __nv_bfloat16 h0 = __float2bfloat16(v.x), h1 = __float2bfloat16(v.y);
    __nv_bfloat16 h2 = __float2bfloat16(v.z), h3 = __float2bfloat16(v.w);
    ho[2 * i + 0] = __nv_bfloat162(h0, h1);
    ho[2 * i + 1] = __nv_bfloat162(h2, h3);
    lo_[2 * i + 0] = __nv_bfloat162(__float2bfloat16(v.x - __bfloat162float(h0)),
                                    __float2bfloat16(v.y - __bfloat162float(h1)));
    lo_[2 * i + 1] = __nv_bfloat162(__float2bfloat16(v.z - __bfloat162float(h2)),
                                    __float2bfloat16(v.w - __bfloat162float(h3)));
}

// ---------------------------------------------------------------------------
// HMMA GEMM body: out = AH@WH^T + AH@WL^T + AL@WH^T (+bias)
// 256 threads = 8 warps, warp grid 4m x 2n, warp tile 16x32, block 64x64.
// FOUR-stage cp.async pipeline, 3 chunks outstanding (wait_group 2) to cover
// L2/DRAM latency; one __syncthreads per chunk.
// Smem rows padded to 40 bf16 (80B) -> conflict-free ldmatrix.
// ---------------------------------------------------------------------------
#define SM_MAT   5120          // 64 * 40 * 2
#define SM_STAGE 20480         // 4 * SM_MAT
#define N_STAGE  4
#define SMEM_BYTES (N_STAGE * SM_STAGE + 256)   // 82176

__device__ __forceinline__ void gemm_body(const __nv_bfloat16* __restrict__ Ahi,
                                          const __nv_bfloat16* __restrict__ Alo,
                                          const __nv_bfloat16* __restrict__ Whi,
                                          const __nv_bfloat16* __restrict__ Wlo,
                                          float* __restrict__ out,
                                          const float* __restrict__ bias,
                                          int m0, int n0, char* sm) {
    uint32_t smu = smem_u32(sm);
    float* bsm = (float*)(sm + N_STAGE * SM_STAGE);

    const int tid = threadIdx.x;
    const int wid = tid >> 5, lane = tid & 31;
    const int wm = (wid & 3) * 16, wn = (wid >> 2) * 32;

    if (tid < 64) bsm[tid] = bias ? bias[n0 + tid] : 0.0f;

    const __nv_bfloat16* aH = Ahi + (size_t)m0 * Cc;
    const __nv_bfloat16* aL = Alo + (size_t)m0 * Cc;
    const __nv_bfloat16* wH = Whi + (size_t)n0 * Cc;
    const __nv_bfloat16* wL = Wlo + (size_t)n0 * Cc;

    const int lrow = tid >> 2, lj = tid & 3;  // 64 rows x 4 vec16 per mat

    auto load_chunk = [&](int s, int c) {
        int k0 = c * 32;
        uint32_t sb = smu + s * SM_STAGE + lrow * 80 + lj * 16;
        size_t go = (size_t)lrow * Cc + k0 + lj * 8;
        cp_async16(sb,              aH + go);
        cp_async16(sb + SM_MAT,     aL + go);
        cp_async16(sb + 2 * SM_MAT, wH + go);
        cp_async16(sb + 3 * SM_MAT, wL + go);
        cp_commit();
    };

    float accA[4][4], accB[4][4];
#pragma unroll
    for (int a = 0; a < 4; a++)
#pragma unroll
        for (int b = 0; b < 4; b++) { accA[a][b] = 0.0f; accB[a][b] = 0.0f; }

    load_chunk(0, 0);
    load_chunk(1, 1);
    load_chunk(2, 2);

    const int r = lane & 15, kh = lane >> 4;

    for (int c = 0; c < 8; c++) {
        // groups complete in order; ensure group c is done
        if (c < 6)      cp_wait2();
        else if (c == 6) cp_wait1();
        else             cp_wait0();
        __syncthreads();
        if (c + 3 < 8) load_chunk((c + 3) % N_STAGE, c + 3);

        int cur = c % N_STAGE;
        uint32_t sAH = smu + cur * SM_STAGE;
        uint32_t sAL = sAH + SM_MAT;
        uint32_t sWH = sAH + 2 * SM_MAT;
        uint32_t sWL = sAH + 3 * SM_MAT;

#pragma unroll
        for (int ks = 0; ks < 2; ks++) {
            int kcol = ks * 16 + kh * 8;
            uint32_t AH[4], AL[4], BH[4][2], BL[4][2];
            {
                uint32_t off = (uint32_t)((wm + r) * 40 + kcol) * 2;
                ldsm4(AH, sAH + off);
                ldsm4(AL, sAL + off);
            }
#pragma unroll
            for (int nj = 0; nj < 2; nj++) {
                uint32_t off = (uint32_t)((wn + nj * 16 + r) * 40 + kcol) * 2;
                uint32_t th[4], tl[4];
                ldsm4(th, sWH + off);
                ldsm4(tl, sWL + off);
                BH[nj * 2 + 0][0] = th[0]; BH[nj * 2 + 0][1] = th[2];
                BH[nj * 2 + 1][0] = th[1]; BH[nj * 2 + 1][1] = th[3];
                BL[nj * 2 + 0][0] = tl[0]; BL[nj * 2 + 0][1] = tl[2];
                BL[nj * 2 + 1][0] = tl[1]; BL[nj * 2 + 1][1] = tl[3];
            }
#pragma unroll
            for (int ni = 0; ni < 4; ni++) mma16816(accA[ni], AH, BH[ni]);
#pragma unroll
            for (int ni = 0; ni < 4; ni++) mma16816(accB[ni], AH, BL[ni]);
#pragma unroll
            for (int ni = 0; ni < 4; ni++) mma16816(accB[ni], AL, BH[ni]);
        }
    }

    const int g = lane >> 2, tg = lane & 3;
#pragma unroll
    for (int ni = 0; ni < 4; ni++) {
        int row = m0 + wm + g;
        int coll = wn + ni * 8 + tg * 2;
        int col = n0 + coll;
        float2 v0 = make_float2(accA[ni][0] + accB[ni][0] + bsm[coll],
                                accA[ni][1] + accB[ni][1] + bsm[coll + 1]);
        float2 v1 = make_float2(accA[ni][2] + accB[ni][2] + bsm[coll],
                                accA[ni][3] + accB[ni][3] + bsm[coll + 1]);
        *(float2*)(out + (size_t)row * Cc + col) = v0;
        *(float2*)(out + (size_t)(row + 8) * Cc + col) = v1;
    }
}

// Fused Q/K/V projections: grid (98, 4, 3); z selects {x@Wq, xkv@Wk, xkv@Wv}.
__global__ __launch_bounds__(256, 2) void gemm_qkv(
    const __nv_bfloat16* __restrict__ xhi, const __nv_bfloat16* __restrict__ xlo,
    const __nv_bfloat16* __restrict__ kvhi, const __nv_bfloat16* __restrict__ kvlo,
    const __nv_bfloat16* __restrict__ whi, const __nv_bfloat16* __restrict__ wlo,
    float* __restrict__ Q, float* __restrict__ K, float* __restrict__ V) {
    extern __shared__ char sm[];
    int z = blockIdx.z;
    const __nv_bfloat16* Ahi = (z == 0) ? xhi : kvhi;
    const __nv_bfloat16* Alo = (z == 0) ? xlo : kvlo;
    const __nv_bfloat16* Wh = whi + (size_t)z * 65536;
    const __nv_bfloat16* Wl = wlo + (size_t)z * 65536;
    float* out = (z == 0) ? Q : (z == 1) ? K : V;
    gemm_body(Ahi, Alo, Wh, Wl, out, nullptr, blockIdx.x * 64, blockIdx.y * 64, sm);
}

// Output projection (with bias).
__global__ __launch_bounds__(256, 2) void gemm_out(
    const __nv_bfloat16* __restrict__ Ahi, const __nv_bfloat16* __restrict__ Alo,
    const __nv_bfloat16* __restrict__ Whi, const __nv_bfloat16* __restrict__ Wlo,
    float* __restrict__ out, const float* __restrict__ bias) {
    extern __shared__ char sm[];
    gemm_body(Ahi, Alo, Whi, Wlo, out, bias, blockIdx.x * 64, blockIdx.y * 64, sm);
}

// ---------------------------------------------------------------------------
// Local windowed attention (radius 3 -> 29 neighbors), SINGLE PASS.
// 8 queries per 128-thread block; 16 threads per query; thread owns 16 ch
// (half a head) -> head dot = 16-ch partial + ONE shfl_xor(1).
// Q is pre-scaled (folded into Wq). No max subtraction (scores O(1)).
// ---------------------------------------------------------------------------
__global__ __launch_bounds__(128) void local_attn(const float* __restrict__ Q,
                                                  const float* __restrict__ K,
                                                  const float* __restrict__ V,
                                                  __nv_bfloat16* __restrict__ Ohi,
                                                  __nv_bfloat16* __restrict__ Olo) {
    const int qi = threadIdx.x >> 4;     // query slot (0..7)
    const int t  = threadIdx.x & 15;     // channel group (16 ch each)
    const int bn = blockIdx.x * 8 + qi;
    const int b  = bn / Nn;
    const int n  = bn - b * Nn;
    const int qy = n / Hh;
    const int qx = n - qy * Hh;

    const size_t coff = (size_t)bn * Cc + t * 16;
    float4 q[4];
#pragma unroll
    for (int j = 0; j < 4; j++) q[j] = *(const float4*)(Q + coff + j * 4);

    const int dy[29] = {-3,-2,-2,-2,-2,-2,-1,-1,-1,-1,-1, 0, 0, 0, 0, 0, 0, 0,
                         1, 1, 1, 1, 1, 2, 2, 2, 2, 2, 3};
    const int dx[29] = { 0,-2,-1, 0, 1, 2,-2,-1, 0, 1, 2,-3,-2,-1, 0, 1, 2, 3,
                        -2,-1, 0, 1, 2,-2,-1, 0, 1, 2, 0};

    const size_t base = (size_t)b * Nn;
    float s = 0.f;
    float4 acc[4];
#pragma unroll
    for (int j = 0; j < 4; j++) acc[j] = make_float4(0.f, 0.f, 0.f, 0.f);

#pragma unroll
    for (int i = 0; i < 29; i++) {
        int ny = qy + dy[i], nx = qx + dx[i];
        bool ok = ((unsigned)ny < (unsigned)Hh) && ((unsigned)nx < (unsigned)Hh);
        int nn = ok ? ny * Hh + nx : n;
        const float* kp = K + (base + nn) * Cc + t * 16;
        const float* vp = V + (base + nn) * Cc + t * 16;
        float p = 0.f;
#pragma unroll
        for (int j = 0; j < 4; j++) {
            float4 k4 = *(const float4*)(kp + j * 4);
            p = fmaf(q[j].x, k4.x, p);
            p = fmaf(q[j].y, k4.y, p);
            p = fmaf(q[j].z, k4.z, p);
            p = fmaf(q[j].w, k4.w, p);
        }
        p += __shfl_xor_sync(0xffffffffu, p, 1);   // partner half of the head
        float e = ok ? __expf(p) : 0.f;
        s += e;
#pragma unroll
        for (int j = 0; j < 4; j++) {
            float4 v4 = *(const float4*)(vp + j * 4);
            acc[j].x = fmaf(e, v4.x, acc[j].x);
            acc[j].y = fmaf(e, v4.y, acc[j].y);
            acc[j].z = fmaf(e, v4.z, acc[j].z);
            acc[j].w = fmaf(e, v4.w, acc[j].w);
        }
    }

    float inv = __fdividef(1.0f, s);
#pragma unroll
    for (int j = 0; j < 4; j++) {
        float4 o = make_float4(acc[j].x * inv, acc[j].y * inv,
                               acc[j].z * inv, acc[j].w * inv);
        __nv_bfloat16 h0 = __float2bfloat16(o.x), h1 = __float2bfloat16(o.y);
        __nv_bfloat16 h2 = __float2bfloat16(o.z), h3 = __float2bfloat16(o.w);
        bf16x4 hv, lv;
        hv.a = __nv_bfloat162(h0, h1);
        hv.b = __nv_bfloat162(h2, h3);
        lv.a = __nv_bfloat162(__float2bfloat16(o.x - __bfloat162float(h0)),
                              __float2bfloat16(o.y - __bfloat162float(h1)));
        lv.b = __nv_bfloat162(__float2bfloat16(o.z - __bfloat162float(h2)),
                              __float2bfloat16(o.w - __bfloat162float(h3)));
        *(bf16x4*)(Ohi + coff + j * 4) = hv;
        *(bf16x4*)(Olo + coff + j * 4) = lv;
    }
}

// ---------------------------------------------------------------------------
extern "C" void kernel_launch(void* const* d_in, const int* in_sizes, int n_in,
                              void* d_out, int out_size) {
    const float* x   = (const float*)d_in[0];
    const float* xkv = (const float*)d_in[1];
    const float* Wq  = (const float*)d_in[2];
    const float* Wk  = (const float*)d_in[3];
    const float* Wv  = (const float*)d_in[4];
    const float* Wp  = (const float*)d_in[5];
    const float* bp  = (const float*)d_in[6];
    float* out = (float*)d_out;

    float *Qp, *Kp, *Vp;
    __nv_bfloat16 *xhi, *xlo, *kvhi, *kvlo, *ahi, *alo, *whi, *wlo;
    cudaGetSymbolAddress((void**)&Qp, g_Q);
    cudaGetSymbolAddress((void**)&Kp, g_K);
    cudaGetSymbolAddress((void**)&Vp, g_V);
    cudaGetSymbolAddress((void**)&xhi, g_xhi);
    cudaGetSymbolAddress((void**)&xlo, g_xlo);
    cudaGetSymbolAddress((void**)&kvhi, g_kvhi);
    cudaGetSymbolAddress((void**)&kvlo, g_kvlo);
    cudaGetSymbolAddress((void**)&ahi, g_ahi);
    cudaGetSymbolAddress((void**)&alo, g_alo);
    cudaGetSymbolAddress((void**)&whi, g_whi);
    cudaGetSymbolAddress((void**)&wlo, g_wlo);

    cudaFuncSetAttribute(gemm_qkv, cudaFuncAttributeMaxDynamicSharedMemorySize, SMEM_BYTES);
    cudaFuncSetAttribute(gemm_out, cudaFuncAttributeMaxDynamicSharedMemorySize, SMEM_BYTES);

    split_all<<<3392, 256>>>((const float4*)x, (const float4*)xkv,
                             (const float4*)Wq, (const float4*)Wk,
                             (const float4*)Wv, (const float4*)Wp,
                             (__nv_bfloat162*)xhi, (__nv_bfloat162*)xlo,
                             (__nv_bfloat162*)kvhi, (__nv_bfloat162*)kvlo,
                             (__nv_bfloat162*)whi, (__nv_bfloat162*)wlo);

    dim3 gqkv(Mtot / 64, Cc / 64, 3);   // (98, 4, 3) = 1176 CTAs
    gemm_qkv<<<gqkv, 256, SMEM_BYTES>>>(xhi, xlo, kvhi, kvlo, whi, wlo, Qp, Kp, Vp);

    local_attn<<<Mtot / 8, 128>>>(Qp, Kp, Vp, ahi, alo);

    dim3 gout(Mtot / 64, Cc / 64);      // (98, 4) = 392 CTAs
    gemm_out<<<gout, 256, SMEM_BYTES>>>(ahi, alo, whi + 196608, wlo + 196608, out, bp);
}

// round 14
// speedup vs baseline: 1.1947x; 1.0520x over previous
#include <cuda_runtime.h>
#include <cuda_bf16.h>
#include <cstdint>

#define Bb 2
#define Nn 3136
#define Cc 256
#define Hh 56
#define Mtot (Bb * Nn)   // 6272

// ---------------- scratch (allocation-free) ----------------
__device__ float g_Q[Mtot * Cc];
__device__ float g_K[Mtot * Cc];
__device__ float g_V[Mtot * Cc];
__device__ __nv_bfloat16 g_xhi[Mtot * Cc], g_xlo[Mtot * Cc];
__device__ __nv_bfloat16 g_kvhi[Mtot * Cc], g_kvlo[Mtot * Cc];
__device__ __nv_bfloat16 g_ahi[Mtot * Cc], g_alo[Mtot * Cc];
__device__ __nv_bfloat16 g_whi[4 * Cc * Cc], g_wlo[4 * Cc * Cc];

// ---------------- portable (sm_80+) PTX helpers ----------------
__device__ __forceinline__ uint32_t smem_u32(const void* p) {
    uint32_t a;
    asm("{ .reg .u64 t; cvta.to.shared.u64 t, %1; cvt.u32.u64 %0, t; }" : "=r"(a) : "l"(p));
    return a;
}
__device__ __forceinline__ void cp_async16(uint32_t dst, const void* src) {
    asm volatile("cp.async.cg.shared.global [%0], [%1], 16;" :: "r"(dst), "l"(src) : "memory");
}
__device__ __forceinline__ void cp_commit() { asm volatile("cp.async.commit_group;" ::: "memory"); }
__device__ __forceinline__ void cp_wait0() { asm volatile("cp.async.wait_group 0;" ::: "memory"); }
__device__ __forceinline__ void ldsm4(uint32_t* r, uint32_t addr) {
    asm volatile("ldmatrix.sync.aligned.m8n8.x4.shared.b16 {%0,%1,%2,%3}, [%4];"
                 : "=r"(r[0]), "=r"(r[1]), "=r"(r[2]), "=r"(r[3]) : "r"(addr));
}
__device__ __forceinline__ void mma16816(float* d, const uint32_t* a, const uint32_t* b) {
    asm volatile(
        "mma.sync.aligned.m16n8k16.row.col.f32.bf16.bf16.f32 "
        "{%0,%1,%2,%3}, {%4,%5,%6,%7}, {%8,%9}, {%0,%1,%2,%3};"
        : "+f"(d[0]), "+f"(d[1]), "+f"(d[2]), "+f"(d[3])
        : "r"(a[0]), "r"(a[1]), "r"(a[2]), "r"(a[3]), "r"(b[0]), "r"(b[1]));
}

struct alignas(8) bf16x4 { __nv_bfloat162 a, b; };

// ---------------------------------------------------------------------------
// Fused split: all 6 fp32 tensors -> (hi, lo) bf16 pairs, one launch.
// Wq is pre-multiplied by the softmax scale (hd^-0.5) so Q comes out scaled.
// ---------------------------------------------------------------------------
__global__ __launch_bounds__(256) void split_all(
    const float4* __restrict__ x, const float4* __restrict__ xkv,
    const float4* __restrict__ wq, const float4* __restrict__ wk,
    const float4* __restrict__ wv, const float4* __restrict__ wp,
    __nv_bfloat162* __restrict__ xhi, __nv_bfloat162* __restrict__ xlo,
    __nv_bfloat162* __restrict__ kvhi, __nv_bfloat162* __restrict__ kvlo,
    __nv_bfloat162* __restrict__ whi, __nv_bfloat162* __restrict__ wlo) {
    int blk = blockIdx.x;
    const float4* src;
    __nv_bfloat162 *ho, *lo_;
    int idx;
    float mul = 1.0f;
    if (blk < 1568) {
        src = x; ho = xhi; lo_ = xlo; idx = blk;
    } else if (blk < 3136) {
        src = xkv; ho = kvhi; lo_ = kvlo; idx = blk - 1568;
    } else {
        int w = (blk - 3136) >> 6;
        idx = (blk - 3136) & 63;
        src = (w == 0) ? wq : (w == 1) ? wk : (w == 2) ? wv : wp;
        ho = whi + w * 32768;
        lo_ = wlo + w * 32768;
        if (w == 0) mul = 0.17677669529663687f;   // fold 32^-0.5 into Wq
    }
    int i = idx * 256 + threadIdx.x;
    float4 v = src[i];
    v.x *= mul; v.y *= mul; v.z *= mul; v.w *= mul;
    __nv_bfloat16 h0 = __float2bfloat16(v.x), h1 = __float2bfloat16(v.y);
    __nv_bfloat16 h2 = __float2bfloat16(v.z), h3 = __float2bfloat16(v.w);
    ho[2 * i + 0] = __nv_bfloat162(h0, h1);
    ho[2 * i + 1] = __nv_bfloat162(h2, h3);
    lo_[2 * i + 0] = __nv_bfloat162(__float2bfloat16(v.x - __bfloat162float(h0)),
                                    __float2bfloat16(v.y - __bfloat162float(h1)));
    lo_[2 * i + 1] = __nv_bfloat162(__float2bfloat16(v.z - __bfloat162float(h2)),
                                    __float2bfloat16(v.w - __bfloat162float(h3)));
}

// ---------------------------------------------------------------------------
// HMMA GEMM body: out = AH@WH^T + AH@WL^T + AL@WH^T (+bias)
// 256 threads = 8 warps, warp grid 4m x 2n, warp tile 16x32, block 64x64.
// K-CHUNK 64: only 4 mainloop iterations (halves barrier/wait rounds).
// 2-stage double buffer; ordering wait -> sync -> issue-next -> compute keeps
// the overwritten stage safe. Smem rows 72 bf16 (144B = 9x16B) -> ldsm
// conflict-free. 74KB smem -> 3 CTAs/SM.
// ---------------------------------------------------------------------------
#define SM_MAT   9216          // 64 rows * 144 B
#define SM_STAGE 36864         // 4 * SM_MAT
#define N_STAGE  2
#define SMEM_BYTES (N_STAGE * SM_STAGE + 256)   // 73984

__device__ __forceinline__ void gemm_body(const __nv_bfloat16* __restrict__ Ahi,
                                          const __nv_bfloat16* __restrict__ Alo,
                                          const __nv_bfloat16* __restrict__ Whi,
                                          const __nv_bfloat16* __restrict__ Wlo,
                                          float* __restrict__ out,
                                          const float* __restrict__ bias,
                                          int m0, int n0, char* sm) {
    uint32_t smu = smem_u32(sm);
    float* bsm = (float*)(sm + N_STAGE * SM_STAGE);

    const int tid = threadIdx.x;
    const int wid = tid >> 5, lane = tid & 31;
    const int wm = (wid & 3) * 16, wn = (wid >> 2) * 32;

    if (tid < 64) bsm[tid] = bias ? bias[n0 + tid] : 0.0f;

    // mat order in smem: 0=AH 1=AL 2=WH 3=WL
    const __nv_bfloat16* mats[4] = {Ahi + (size_t)m0 * Cc, Alo + (size_t)m0 * Cc,
                                    Whi + (size_t)n0 * Cc, Wlo + (size_t)n0 * Cc};

    // Per-thread: rows r0 = tid>>3 and r0+32, vec column j = tid&7, all 4 mats.
    const int r0 = tid >> 3, lj = tid & 7;

    auto load_chunk = [&](int s, int c) {
        int k0 = c * 64;
        uint32_t sb = smu + s * SM_STAGE;
#pragma unroll
        for (int m = 0; m < 4; m++) {
            const __nv_bfloat16* g = mats[m] + k0 + lj * 8;
            cp_async16(sb + m * SM_MAT + r0 * 144 + lj * 16,
                       g + (size_t)r0 * Cc);
            cp_async16(sb + m * SM_MAT + (r0 + 32) * 144 + lj * 16,
                       g + (size_t)(r0 + 32) * Cc);
        }
        cp_commit();
    };

    float accA[4][4], accB[4][4];
#pragma unroll
    for (int a = 0; a < 4; a++)
#pragma unroll
        for (int b = 0; b < 4; b++) { accA[a][b] = 0.0f; accB[a][b] = 0.0f; }

    load_chunk(0, 0);

    const int r = lane & 15, kh = lane >> 4;

    for (int c = 0; c < 4; c++) {
        cp_wait0();                 // chunk c landed
        __syncthreads();            // all warps done reading the other stage
        if (c + 1 < 4) load_chunk((c + 1) & 1, c + 1);

        uint32_t sAH = smu + (c & 1) * SM_STAGE;
        uint32_t sAL = sAH + SM_MAT;
        uint32_t sWH = sAH + 2 * SM_MAT;
        uint32_t sWL = sAH + 3 * SM_MAT;

#pragma unroll
        for (int ks = 0; ks < 4; ks++) {
            int kcol = ks * 16 + kh * 8;
            uint32_t AH[4], AL[4], BH[4][2], BL[4][2];
            {
                uint32_t off = (uint32_t)((wm + r) * 72 + kcol) * 2;
                ldsm4(AH, sAH + off);
                ldsm4(AL, sAL + off);
            }
#pragma unroll
            for (int nj = 0; nj < 2; nj++) {
                uint32_t off = (uint32_t)((wn + nj * 16 + r) * 72 + kcol) * 2;
                uint32_t th[4], tl[4];
                ldsm4(th, sWH + off);
                ldsm4(tl, sWL + off);
                BH[nj * 2 + 0][0] = th[0]; BH[nj * 2 + 0][1] = th[2];
                BH[nj * 2 + 1][0] = th[1]; BH[nj * 2 + 1][1] = th[3];
                BL[nj * 2 + 0][0] = tl[0]; BL[nj * 2 + 0][1] = tl[2];
                BL[nj * 2 + 1][0] = tl[1]; BL[nj * 2 + 1][1] = tl[3];
            }
#pragma unroll
            for (int ni = 0; ni < 4; ni++) mma16816(accA[ni], AH, BH[ni]);
#pragma unroll
            for (int ni = 0; ni < 4; ni++) mma16816(accB[ni], AH, BL[ni]);
#pragma unroll
            for (int ni = 0; ni < 4; ni++) mma16816(accB[ni], AL, BH[ni]);
        }
    }

    const int g = lane >> 2, tg = lane & 3;
#pragma unroll
    for (int ni = 0; ni < 4; ni++) {
        int row = m0 + wm + g;
        int coll = wn + ni * 8 + tg * 2;
        int col = n0 + coll;
        float2 v0 = make_float2(accA[ni][0] + accB[ni][0] + bsm[coll],
                                accA[ni][1] + accB[ni][1] + bsm[coll + 1]);
        float2 v1 = make_float2(accA[ni][2] + accB[ni][2] + bsm[coll],
                                accA[ni][3] + accB[ni][3] + bsm[coll + 1]);
        *(float2*)(out + (size_t)row * Cc + col) = v0;
        *(float2*)(out + (size_t)(row + 8) * Cc + col) = v1;
    }
}

// Fused Q/K/V projections: grid (98, 4, 3); z selects {x@Wq, xkv@Wk, xkv@Wv}.
__global__ __launch_bounds__(256, 3) void gemm_qkv(
    const __nv_bfloat16* __restrict__ xhi, const __nv_bfloat16* __restrict__ xlo,
    const __nv_bfloat16* __restrict__ kvhi, const __nv_bfloat16* __restrict__ kvlo,
    const __nv_bfloat16* __restrict__ whi, const __nv_bfloat16* __restrict__ wlo,
    float* __restrict__ Q, float* __restrict__ K, float* __restrict__ V) {
    extern __shared__ char sm[];
    int z = blockIdx.z;
    const __nv_bfloat16* Ahi = (z == 0) ? xhi : kvhi;
    const __nv_bfloat16* Alo = (z == 0) ? xlo : kvlo;
    const __nv_bfloat16* Wh = whi + (size_t)z * 65536;
    const __nv_bfloat16* Wl = wlo + (size_t)z * 65536;
    float* out = (z == 0) ? Q : (z == 1) ? K : V;
    gemm_body(Ahi, Alo, Wh, Wl, out, nullptr, blockIdx.x * 64, blockIdx.y * 64, sm);
}

// Output projection (with bias).
__global__ __launch_bounds__(256, 3) void gemm_out(
    const __nv_bfloat16* __restrict__ Ahi, const __nv_bfloat16* __restrict__ Alo,
    const __nv_bfloat16* __restrict__ Whi, const __nv_bfloat16* __restrict__ Wlo,
    float* __restrict__ out, const float* __restrict__ bias) {
    extern __shared__ char sm[];
    gemm_body(Ahi, Alo, Whi, Wlo, out, bias, blockIdx.x * 64, blockIdx.y * 64, sm);
}

// ---------------------------------------------------------------------------
// Local windowed attention (radius 3 -> 29 neighbors), SINGLE PASS.
// 8 queries per 128-thread block; 16 threads per query; thread owns 16 ch
// (half a head) -> head dot = 16-ch partial + ONE shfl_xor(1).
// Q is pre-scaled (folded into Wq). No max subtraction (scores O(1)).
// ---------------------------------------------------------------------------
__global__ __launch_bounds__(128) void local_attn(const float* __restrict__ Q,
                                                  const float* __restrict__ K,
                                                  const float* __restrict__ V,
                                                  __nv_bfloat16* __restrict__ Ohi,
                                                  __nv_bfloat16* __restrict__ Olo) {
    const int qi = threadIdx.x >> 4;     // query slot (0..7)
    const int t  = threadIdx.x & 15;     // channel group (16 ch each)
    const int bn = blockIdx.x * 8 + qi;
    const int b  = bn / Nn;
    const int n  = bn - b * Nn;
    const int qy = n / Hh;
    const int qx = n - qy * Hh;

    const size_t coff = (size_t)bn * Cc + t * 16;
    float4 q[4];
#pragma unroll
    for (int j = 0; j < 4; j++) q[j] = *(const float4*)(Q + coff + j * 4);

    const int dy[29] = {-3,-2,-2,-2,-2,-2,-1,-1,-1,-1,-1, 0, 0, 0, 0, 0, 0, 0,
                         1, 1, 1, 1, 1, 2, 2, 2, 2, 2, 3};
    const int dx[29] = { 0,-2,-1, 0, 1, 2,-2,-1, 0, 1, 2,-3,-2,-1, 0, 1, 2, 3,
                        -2,-1, 0, 1, 2,-2,-1, 0, 1, 2, 0};

    const size_t base = (size_t)b * Nn;
    float s = 0.f;
    float4 acc[4];
#pragma unroll
    for (int j = 0; j < 4; j++) acc[j] = make_float4(0.f, 0.f, 0.f, 0.f);

#pragma unroll
    for (int i = 0; i < 29; i++) {
        int ny = qy + dy[i], nx = qx + dx[i];
        bool ok = ((unsigned)ny < (unsigned)Hh) && ((unsigned)nx < (unsigned)Hh);
        int nn = ok ? ny * Hh + nx : n;
        const float* kp = K + (base + nn) * Cc + t * 16;
        const float* vp = V + (base + nn) * Cc + t * 16;
        float p = 0.f;
#pragma unroll
        for (int j = 0; j < 4; j++) {
            float4 k4 = *(const float4*)(kp + j * 4);
            p = fmaf(q[j].x, k4.x, p);
            p = fmaf(q[j].y, k4.y, p);
            p = fmaf(q[j].z, k4.z, p);
            p = fmaf(q[j].w, k4.w, p);
        }
        p += __shfl_xor_sync(0xffffffffu, p, 1);   // partner half of the head
        float e = ok ? __expf(p) : 0.f;
        s += e;
#pragma unroll
        for (int j = 0; j < 4; j++) {
            float4 v4 = *(const float4*)(vp + j * 4);
            acc[j].x = fmaf(e, v4.x, acc[j].x);
            acc[j].y = fmaf(e, v4.y, acc[j].y);
            acc[j].z = fmaf(e, v4.z, acc[j].z);
            acc[j].w = fmaf(e, v4.w, acc[j].w);
        }
    }

    float inv = __fdividef(1.0f, s);
#pragma unroll
    for (int j = 0; j < 4; j++) {
        float4 o = make_float4(acc[j].x * inv, acc[j].y * inv,
                               acc[j].z * inv, acc[j].w * inv);
        __nv_bfloat16 h0 = __float2bfloat16(o.x), h1 = __float2bfloat16(o.y);
        __nv_bfloat16 h2 = __float2bfloat16(o.z), h3 = __float2bfloat16(o.w);
        bf16x4 hv, lv;
        hv.a = __nv_bfloat162(h0, h1);
        hv.b = __nv_bfloat162(h2, h3);
        lv.a = __nv_bfloat162(__float2bfloat16(o.x - __bfloat162float(h0)),
                              __float2bfloat16(o.y - __bfloat162float(h1)));
        lv.b = __nv_bfloat162(__float2bfloat16(o.z - __bfloat162float(h2)),
                              __float2bfloat16(o.w - __bfloat162float(h3)));
        *(bf16x4*)(Ohi + coff + j * 4) = hv;
        *(bf16x4*)(Olo + coff + j * 4) = lv;
    }
}

// ---------------------------------------------------------------------------
extern "C" void kernel_launch(void* const* d_in, const int* in_sizes, int n_in,
                              void* d_out, int out_size) {
    const float* x   = (const float*)d_in[0];
    const float* xkv = (const float*)d_in[1];
    const float* Wq  = (const float*)d_in[2];
    const float* Wk  = (const float*)d_in[3];
    const float* Wv  = (const float*)d_in[4];
    const float* Wp  = (const float*)d_in[5];
    const float* bp  = (const float*)d_in[6];
    float* out = (float*)d_out;

    float *Qp, *Kp, *Vp;
    __nv_bfloat16 *xhi, *xlo, *kvhi, *kvlo, *ahi, *alo, *whi, *wlo;
    cudaGetSymbolAddress((void**)&Qp, g_Q);
    cudaGetSymbolAddress((void**)&Kp, g_K);
    cudaGetSymbolAddress((void**)&Vp, g_V);
    cudaGetSymbolAddress((void**)&xhi, g_xhi);
    cudaGetSymbolAddress((void**)&xlo, g_xlo);
    cudaGetSymbolAddress((void**)&kvhi, g_kvhi);
    cudaGetSymbolAddress((void**)&kvlo, g_kvlo);
    cudaGetSymbolAddress((void**)&ahi, g_ahi);
    cudaGetSymbolAddress((void**)&alo, g_alo);
    cudaGetSymbolAddress((void**)&whi, g_whi);
    cudaGetSymbolAddress((void**)&wlo, g_wlo);

    cudaFuncSetAttribute(gemm_qkv, cudaFuncAttributeMaxDynamicSharedMemorySize, SMEM_BYTES);
    cudaFuncSetAttribute(gemm_out, cudaFuncAttributeMaxDynamicSharedMemorySize, SMEM_BYTES);

    split_all<<<3392, 256>>>((const float4*)x, (const float4*)xkv,
                             (const float4*)Wq, (const float4*)Wk,
                             (const float4*)Wv, (const float4*)Wp,
                             (__nv_bfloat162*)xhi, (__nv_bfloat162*)xlo,
                             (__nv_bfloat162*)kvhi, (__nv_bfloat162*)kvlo,
                             (__nv_bfloat162*)whi, (__nv_bfloat162*)wlo);

    dim3 gqkv(Mtot / 64, Cc / 64, 3);   // (98, 4, 3) = 1176 CTAs
    gemm_qkv<<<gqkv, 256, SMEM_BYTES>>>(xhi, xlo, kvhi, kvlo, whi, wlo, Qp, Kp, Vp);

    local_attn<<<Mtot / 8, 128>>>(Qp, Kp, Vp, ahi, alo);

    dim3 gout(Mtot / 64, Cc / 64);      // (98, 4) = 392 CTAs
    gemm_out<<<gout, 256, SMEM_BYTES>>>(ahi, alo, whi + 196608, wlo + 196608, out, bp);
}